// round 3
// baseline (speedup 1.0000x reference)
#include <cuda_runtime.h>

// TemporalDecay: out = h + (1-M)*gamma*(h_fwd - h),  gamma = exp(-relu(delta*W + b))
// h_fwd[b,t,j] = h[b, t-(delta-1), j],  delta in {1..4} clamped to t+1.
// Key facts exploited:
//   * delta==1  => out == h exactly (mask algebra) -> gamma(1) never needed
//   * delta<=4  => h_fwd is one of the last 3 rows -> keep them in REGISTERS
//     by marching t sequentially per thread: NO gather loads at all.
//   * W,b fixed per thread -> gamma(2),gamma(3),gamma(4) precomputed per lane.
// All remaining traffic is perfectly coalesced float4 streaming.

#define B_    32
#define T_    2048
#define KD_   256
#define NVCOL 64              // KD_/4 float4 columns
#define SEG   32              // t-steps per thread
#define NSEG  (T_ / SEG)      // 64
#define TPB   128

__device__ __forceinline__ float lane_blend(float ha, float p1, float p2, float p3,
                                            float dl, float mm,
                                            float g2, float g3, float g4)
{
    const int di = (int)dl;
    const float hp  = (di == 2) ? p1 : ((di == 3) ? p2 : p3);
    const float gam = (di == 2) ? g2 : ((di == 3) ? g3 : g4);
    const float coef = (mm == 0.0f && di > 1) ? gam : 0.0f;
    return fmaf(coef, hp - ha, ha);
}

__device__ __forceinline__ float4 vec_blend(float4 ha, float4 p1, float4 p2, float4 p3,
                                            float4 dl, float4 mm,
                                            float4 g2, float4 g3, float4 g4)
{
    float4 o;
    o.x = lane_blend(ha.x, p1.x, p2.x, p3.x, dl.x, mm.x, g2.x, g3.x, g4.x);
    o.y = lane_blend(ha.y, p1.y, p2.y, p3.y, dl.y, mm.y, g2.y, g3.y, g4.y);
    o.z = lane_blend(ha.z, p1.z, p2.z, p3.z, dl.z, mm.z, g2.z, g3.z, g4.z);
    o.w = lane_blend(ha.w, p1.w, p2.w, p3.w, dl.w, mm.w, g2.w, g3.w, g4.w);
    return o;
}

__device__ __forceinline__ float gexp(float d, float w, float b)
{
    return __expf(-fmaxf(fmaf(d, w, b), 0.0f));
}

__global__ __launch_bounds__(TPB)
void temporal_decay_kernel(const float4* __restrict__ h4,
                           const float4* __restrict__ d4,
                           const float4* __restrict__ m4,
                           const float4* __restrict__ w4,
                           const float4* __restrict__ b4,
                           float4* __restrict__ out4)
{
    const int g      = blockIdx.x * TPB + threadIdx.x;
    const int v      = g & (NVCOL - 1);        // vec column 0..63
    const int rowgrp = g >> 6;                 // b*NSEG + s
    const int row0   = rowgrp * SEG;           // global start row (b*T + t0)
    const int t0     = (row0 & (T_ - 1));      // t0 within sequence

    // Per-lane gamma for delta = 2,3,4 (delta==1 path never uses gamma).
    const float4 ww = w4[v];
    const float4 bb = b4[v];
    float4 g2, g3, g4;
    g2.x = gexp(2.f, ww.x, bb.x); g2.y = gexp(2.f, ww.y, bb.y);
    g2.z = gexp(2.f, ww.z, bb.z); g2.w = gexp(2.f, ww.w, bb.w);
    g3.x = gexp(3.f, ww.x, bb.x); g3.y = gexp(3.f, ww.y, bb.y);
    g3.z = gexp(3.f, ww.z, bb.z); g3.w = gexp(3.f, ww.w, bb.w);
    g4.x = gexp(4.f, ww.x, bb.x); g4.y = gexp(4.f, ww.y, bb.y);
    g4.z = gexp(4.f, ww.z, bb.z); g4.w = gexp(4.f, ww.w, bb.w);

    // History h[t0-1], h[t0-2], h[t0-3] (clamped at sequence start; clamped
    // values are only read when delta is itself clamped, giving h[0] = correct).
    const int hb = (t0 == 0) ? row0 : -1;  // sentinel
    float4 p1 = h4[(size_t)((hb >= 0) ? hb : row0 - 1) * NVCOL + v];
    float4 p2 = h4[(size_t)((hb >= 0) ? hb : row0 - 2) * NVCOL + v];
    float4 p3 = h4[(size_t)((hb >= 0) ? hb : row0 - 3) * NVCOL + v];

    size_t hidx = (size_t)row0 * NVCOL + v;
    size_t didx = (size_t)row0 * (NVCOL / 4) + (v & 15);

    #pragma unroll 2
    for (int tb = 0; tb < SEG; tb += 4) {
        // Issue all 12 loads up front (independent -> high MLP).
        const float4 a0 = h4[hidx];
        const float4 a1 = h4[hidx + NVCOL];
        const float4 a2 = h4[hidx + 2 * NVCOL];
        const float4 a3 = h4[hidx + 3 * NVCOL];
        const float4 l0 = d4[didx];
        const float4 l1 = d4[didx + 16];
        const float4 l2 = d4[didx + 32];
        const float4 l3 = d4[didx + 48];
        const float4 q0 = m4[didx];
        const float4 q1 = m4[didx + 16];
        const float4 q2 = m4[didx + 32];
        const float4 q3 = m4[didx + 48];

        out4[hidx]             = vec_blend(a0, p1, p2, p3, l0, q0, g2, g3, g4);
        out4[hidx + NVCOL]     = vec_blend(a1, a0, p1, p2, l1, q1, g2, g3, g4);
        out4[hidx + 2 * NVCOL] = vec_blend(a2, a1, a0, p1, l2, q2, g2, g3, g4);
        out4[hidx + 3 * NVCOL] = vec_blend(a3, a2, a1, a0, l3, q3, g2, g3, g4);

        p1 = a3; p2 = a2; p3 = a1;
        hidx += 4 * NVCOL;
        didx += 64;
    }
}

extern "C" void kernel_launch(void* const* d_in, const int* in_sizes, int n_in,
                              void* d_out, int out_size)
{
    const float* h_a    = (const float*)d_in[0];
    const float* deltas = (const float*)d_in[1];
    const float* M      = (const float*)d_in[2];
    const float* W      = (const float*)d_in[3];
    const float* bvec   = (const float*)d_in[4];
    float* out          = (float*)d_out;

    const int nthreads = B_ * NSEG * NVCOL;    // 131072
    const int blocks   = nthreads / TPB;       // 1024

    temporal_decay_kernel<<<blocks, TPB>>>(
        (const float4*)h_a, (const float4*)deltas, (const float4*)M,
        (const float4*)W, (const float4*)bvec, (float4*)out);
}